// round 6
// baseline (speedup 1.0000x reference)
#include <cuda_runtime.h>

#define NHID 1024
#define NTPC 225
#define NCLS 224
#define BATCH 2048
#define SBT 16
#define SLSTRIDE 232
#define GK 8            // k-group for software pipeline (fits 64-reg cap)
#define SMEM_BYTES (NHID * SBT * 4)   // 64 KB

// ---------------- scratch ----------------
__device__ int   g_count[NCLS];
__device__ int   g_offset[NCLS];
__device__ int   g_order[BATCH];
__device__ int   g_class[BATCH];
__device__ int   g_tok[BATCH];
__device__ float g_topprob[BATCH];

// ---------------- f32x2 helpers ----------------
__device__ __forceinline__ unsigned long long pack2(float a) {
    unsigned long long r;
    asm("mov.b64 %0, {%1, %1};" : "=l"(r) : "r"(__float_as_uint(a)));
    return r;
}
__device__ __forceinline__ void fma2(unsigned long long& a, unsigned long long x,
                                     unsigned long long w) {
    asm("fma.rn.f32x2 %0, %1, %2, %0;" : "+l"(a) : "l"(x), "l"(w));
}
__device__ __forceinline__ float lo2(unsigned long long a) { return __uint_as_float((unsigned)a); }
__device__ __forceinline__ float hi2(unsigned long long a) { return __uint_as_float((unsigned)(a >> 32)); }

// ---------------- fused preprocessing ----------------
__global__ __launch_bounds__(256) void k_prep(const int* __restrict__ labels) {
    __shared__ int scount[NCLS];
    __shared__ int soff[NCLS];
    __shared__ int sfill[NCLS];
    __shared__ int swsum[8];
    int tid = threadIdx.x;
    int lane = tid & 31, wid = tid >> 5;
    if (tid < NCLS) { scount[tid] = 0; sfill[tid] = 0; }
    __syncthreads();

    for (int i = tid; i < BATCH; i += 256) {
        int l = labels[i];
        int c = l / NTPC;
        c = min(max(c, 0), NCLS - 1);
        g_class[i] = c;
        g_tok[i]   = l - c * NTPC;
        atomicAdd(&scount[c], 1);
    }
    __syncthreads();

    int incl = 0, own = 0;
    if (tid < NCLS) {
        own = scount[tid];
        incl = own;
        #pragma unroll
        for (int o = 1; o < 32; o <<= 1) {
            int nb = __shfl_up_sync(0xffffffffu, incl, o);
            if (lane >= o) incl += nb;
        }
        if (lane == 31) swsum[wid] = incl;
    }
    __syncthreads();
    if (tid == 0) {
        int acc = 0;
        #pragma unroll
        for (int w = 0; w < 7; w++) { int t = swsum[w]; swsum[w] = acc; acc += t; }
    }
    __syncthreads();
    if (tid < NCLS) {
        int excl = incl - own + swsum[wid];
        soff[tid] = excl;
        g_count[tid]  = own;
        g_offset[tid] = excl;
    }
    __syncthreads();

    for (int i = tid; i < BATCH; i += 256) {
        int c = g_class[i];
        int pos = soff[c] + atomicAdd(&sfill[c], 1);
        g_order[pos] = i;
    }
}

// ---------------- top ----------------
__global__ __launch_bounds__(512, 2) void k_top(const float* __restrict__ x,
                                                const float* __restrict__ W,
                                                const float* __restrict__ b) {
    extern __shared__ float smem[];
    float* sx = smem;
    float* sl = smem;
    int tid  = threadIdx.x;
    int base = blockIdx.x * SBT;
    int wg   = tid >> 8;        // 0 or 1
    int col  = tid & 255;

    for (int idx = tid; idx < (NHID / 4) * SBT; idx += 512) {
        int u  = idx / (NHID / 4);
        int k4 = (idx % (NHID / 4)) * 4;
        float4 v = *(const float4*)&x[(size_t)(base + u) * NHID + k4];
        sx[(k4 + 0) * SBT + u] = v.x;
        sx[(k4 + 1) * SBT + u] = v.y;
        sx[(k4 + 2) * SBT + u] = v.z;
        sx[(k4 + 3) * SBT + u] = v.w;
    }
    __syncthreads();

    unsigned long long acc[4];
    if (col < NCLS) {
        const float* wp = W + col;
        unsigned long long bb = pack2(b[col]);
        #pragma unroll
        for (int j = 0; j < 4; j++) acc[j] = bb;

        float wbuf[GK];
        #pragma unroll
        for (int g = 0; g < GK; g++) wbuf[g] = __ldg(wp + g * NCLS);

        for (int k0 = 0; k0 < NHID; k0 += GK) {
            float wnxt[GK];
            bool more = (k0 + GK < NHID);
            #pragma unroll
            for (int g = 0; g < GK; g++)
                wnxt[g] = more ? __ldg(wp + (k0 + GK + g) * NCLS) : 0.f;
            #pragma unroll
            for (int g = 0; g < GK; g++) {
                unsigned long long wv = pack2(wbuf[g]);
                const ulonglong2* xp = (const ulonglong2*)(sx + (k0 + g) * SBT);
                #pragma unroll
                for (int j = 0; j < 2; j++) {
                    ulonglong2 p = xp[wg * 2 + j];
                    fma2(acc[2 * j + 0], p.x, wv);
                    fma2(acc[2 * j + 1], p.y, wv);
                }
            }
            #pragma unroll
            for (int g = 0; g < GK; g++) wbuf[g] = wnxt[g];
        }
    }
    __syncthreads();

    if (col < NCLS) {
        #pragma unroll
        for (int j = 0; j < 2; j++) {
            int s0 = 8 * wg + 4 * j;
            sl[(s0 + 0) * SLSTRIDE + col] = lo2(acc[2 * j + 0]);
            sl[(s0 + 1) * SLSTRIDE + col] = hi2(acc[2 * j + 0]);
            sl[(s0 + 2) * SLSTRIDE + col] = lo2(acc[2 * j + 1]);
            sl[(s0 + 3) * SLSTRIDE + col] = hi2(acc[2 * j + 1]);
        }
    }
    __syncthreads();

    int wid = tid >> 5, lane = tid & 31;   // 16 warps -> 16 samples
    if (wid < SBT) {
        int i = base + wid;
        float v[7];
        #pragma unroll
        for (int j = 0; j < 7; j++) v[j] = sl[wid * SLSTRIDE + lane + j * 32];
        float m = v[0];
        #pragma unroll
        for (int j = 1; j < 7; j++) m = fmaxf(m, v[j]);
        #pragma unroll
        for (int o = 16; o > 0; o >>= 1) m = fmaxf(m, __shfl_xor_sync(0xffffffffu, m, o));
        float sum = 0.f;
        #pragma unroll
        for (int j = 0; j < 7; j++) sum += __expf(v[j] - m);
        #pragma unroll
        for (int o = 16; o > 0; o >>= 1) sum += __shfl_xor_sync(0xffffffffu, sum, o);
        if (lane == 0) {
            int c = g_class[i];
            g_topprob[i] = __expf(sl[wid * SLSTRIDE + c] - m) / sum;
        }
    }
}

// ---------------- bottom ----------------
__global__ __launch_bounds__(512, 2) void k_bottom(const float* __restrict__ x,
                                                   const float* __restrict__ W,
                                                   const float* __restrict__ b,
                                                   float* __restrict__ out) {
    extern __shared__ float smem[];
    float* sx = smem;
    float* sl = smem;
    __shared__ int sid[SBT];

    int c   = blockIdx.x;
    int n   = g_count[c];
    int off = g_offset[c];
    int tid = threadIdx.x;
    int wg  = tid >> 8;
    int col = tid & 255;
    const float* Wc = W + (size_t)c * NHID * NTPC;

    for (int chunk = blockIdx.y; chunk * SBT < n; chunk += gridDim.y) {
        int nv = min(SBT, n - chunk * SBT);
        if (tid < SBT) sid[tid] = (tid < nv) ? g_order[off + chunk * SBT + tid] : 0;
        __syncthreads();

        for (int idx = tid; idx < (NHID / 4) * SBT; idx += 512) {
            int u  = idx / (NHID / 4);
            int k4 = (idx % (NHID / 4)) * 4;
            float4 v = (u < nv) ? *(const float4*)&x[(size_t)sid[u] * NHID + k4]
                                : make_float4(0.f, 0.f, 0.f, 0.f);
            sx[(k4 + 0) * SBT + u] = v.x;
            sx[(k4 + 1) * SBT + u] = v.y;
            sx[(k4 + 2) * SBT + u] = v.z;
            sx[(k4 + 3) * SBT + u] = v.w;
        }
        __syncthreads();

        unsigned long long acc[4];
        if (col < NTPC) {
            const float* wp = Wc + col;
            unsigned long long bb = pack2(b[c * NTPC + col]);
            #pragma unroll
            for (int j = 0; j < 4; j++) acc[j] = bb;

            float wbuf[GK];
            #pragma unroll
            for (int g = 0; g < GK; g++) wbuf[g] = __ldg(wp + g * NTPC);

            for (int k0 = 0; k0 < NHID; k0 += GK) {
                float wnxt[GK];
                bool more = (k0 + GK < NHID);
                #pragma unroll
                for (int g = 0; g < GK; g++)
                    wnxt[g] = more ? __ldg(wp + (k0 + GK + g) * NTPC) : 0.f;
                #pragma unroll
                for (int g = 0; g < GK; g++) {
                    unsigned long long wv = pack2(wbuf[g]);
                    const ulonglong2* xp = (const ulonglong2*)(sx + (k0 + g) * SBT);
                    #pragma unroll
                    for (int j = 0; j < 2; j++) {
                        ulonglong2 p = xp[wg * 2 + j];
                        fma2(acc[2 * j + 0], p.x, wv);
                        fma2(acc[2 * j + 1], p.y, wv);
                    }
                }
                #pragma unroll
                for (int g = 0; g < GK; g++) wbuf[g] = wnxt[g];
            }
        }
        __syncthreads();

        if (col < NTPC) {
            #pragma unroll
            for (int j = 0; j < 2; j++) {
                int s0 = 8 * wg + 4 * j;
                sl[(s0 + 0) * SLSTRIDE + col] = lo2(acc[2 * j + 0]);
                sl[(s0 + 1) * SLSTRIDE + col] = hi2(acc[2 * j + 0]);
                sl[(s0 + 2) * SLSTRIDE + col] = lo2(acc[2 * j + 1]);
                sl[(s0 + 3) * SLSTRIDE + col] = hi2(acc[2 * j + 1]);
            }
        }
        __syncthreads();

        int wid = tid >> 5, lane = tid & 31;
        if (wid < nv) {
            int i = sid[wid];
            float v[8];
            #pragma unroll
            for (int j = 0; j < 8; j++) {
                int idx = lane + j * 32;
                v[j] = (idx < NTPC) ? sl[wid * SLSTRIDE + idx] : -1e30f;
            }
            float m = v[0];
            #pragma unroll
            for (int j = 1; j < 8; j++) m = fmaxf(m, v[j]);
            #pragma unroll
            for (int o = 16; o > 0; o >>= 1) m = fmaxf(m, __shfl_xor_sync(0xffffffffu, m, o));
            float sum = 0.f;
            #pragma unroll
            for (int j = 0; j < 8; j++) {
                int idx = lane + j * 32;
                sum += (idx < NTPC) ? __expf(v[j] - m) : 0.f;
            }
            #pragma unroll
            for (int o = 16; o > 0; o >>= 1) sum += __shfl_xor_sync(0xffffffffu, sum, o);
            if (lane == 0) {
                int tp = g_tok[i];
                float bprob = __expf(sl[wid * SLSTRIDE + tp] - m) / sum;
                out[i] = g_topprob[i] * bprob;
            }
        }
        __syncthreads();
    }
}

// ---------------- launch ----------------
extern "C" void kernel_launch(void* const* d_in, const int* in_sizes, int n_in,
                              void* d_out, int out_size) {
    const float* inputs = (const float*)d_in[0];
    const int*   labels = (const int*)d_in[1];
    const float* topW   = (const float*)d_in[2];
    const float* topB   = (const float*)d_in[3];
    const float* botW   = (const float*)d_in[4];
    const float* botB   = (const float*)d_in[5];
    float*       out    = (float*)d_out;

    cudaFuncSetAttribute(k_top,    cudaFuncAttributeMaxDynamicSharedMemorySize, SMEM_BYTES);
    cudaFuncSetAttribute(k_bottom, cudaFuncAttributeMaxDynamicSharedMemorySize, SMEM_BYTES);

    k_prep<<<1, 256>>>(labels);
    k_top<<<BATCH / SBT, 512, SMEM_BYTES>>>(inputs, topW, topB);
    k_bottom<<<dim3(NCLS, 2), 512, SMEM_BYTES>>>(inputs, botW, botB, out);
}

// round 7
// speedup vs baseline: 1.1300x; 1.1300x over previous
#include <cuda_runtime.h>

#define NHID 1024
#define NTPC 225
#define NCLS 224
#define BATCH 2048
#define SBT 16
#define SLSTRIDE 232
#define GK 16
#define NTOPITEMS (BATCH / SBT)    // 128 top tiles
#define MAINBLOCKS 296             // 148 SMs * occ 2
#define SMEM_BYTES (NHID * SBT * 4)

// ---------------- scratch ----------------
__device__ int   g_count[NCLS];
__device__ int   g_offset[NCLS];
__device__ int   g_order[BATCH];
__device__ int   g_class[BATCH];
__device__ int   g_tok[BATCH];
__device__ float g_topprob[BATCH];
__device__ int   g_work;
__device__ int   g_nbot;
__device__ int   g_bitem[512];     // (class<<8)|chunk

// ---------------- f32x2 helpers ----------------
__device__ __forceinline__ unsigned long long pack2(float a) {
    unsigned long long r;
    asm("mov.b64 %0, {%1, %1};" : "=l"(r) : "r"(__float_as_uint(a)));
    return r;
}
__device__ __forceinline__ void fma2(unsigned long long& a, unsigned long long x,
                                     unsigned long long w) {
    asm("fma.rn.f32x2 %0, %1, %2, %0;" : "+l"(a) : "l"(x), "l"(w));
}
__device__ __forceinline__ float lo2(unsigned long long a) { return __uint_as_float((unsigned)a); }
__device__ __forceinline__ float hi2(unsigned long long a) { return __uint_as_float((unsigned)(a >> 32)); }

// ---------------- preprocessing: classify, sort, emit work items ----------------
__global__ __launch_bounds__(256) void k_prep(const int* __restrict__ labels) {
    __shared__ int scount[NCLS];
    __shared__ int soff[NCLS];
    __shared__ int sfill[NCLS];
    __shared__ int swsum[8];
    int tid = threadIdx.x;
    int lane = tid & 31, wid = tid >> 5;
    if (tid == 0) { g_work = 0; g_nbot = 0; }
    if (tid < NCLS) { scount[tid] = 0; sfill[tid] = 0; }
    __syncthreads();

    for (int i = tid; i < BATCH; i += 256) {
        int l = labels[i];
        int c = l / NTPC;
        c = min(max(c, 0), NCLS - 1);
        g_class[i] = c;
        g_tok[i]   = l - c * NTPC;
        atomicAdd(&scount[c], 1);
    }
    __syncthreads();

    int incl = 0, own = 0;
    if (tid < NCLS) {
        own = scount[tid];
        incl = own;
        #pragma unroll
        for (int o = 1; o < 32; o <<= 1) {
            int nb = __shfl_up_sync(0xffffffffu, incl, o);
            if (lane >= o) incl += nb;
        }
        if (lane == 31) swsum[wid] = incl;
    }
    __syncthreads();
    if (tid == 0) {
        int acc = 0;
        #pragma unroll
        for (int w = 0; w < 7; w++) { int t = swsum[w]; swsum[w] = acc; acc += t; }
    }
    __syncthreads();
    if (tid < NCLS) {
        int excl = incl - own + swsum[wid];
        soff[tid] = excl;
        g_count[tid]  = own;
        g_offset[tid] = excl;
        int nch = (own + SBT - 1) / SBT;
        if (nch > 0) {
            int p = atomicAdd(&g_nbot, nch);
            for (int j = 0; j < nch; j++) g_bitem[p + j] = (tid << 8) | j;
        }
    }
    __syncthreads();

    for (int i = tid; i < BATCH; i += 256) {
        int c = g_class[i];
        int pos = soff[c] + atomicAdd(&sfill[c], 1);
        g_order[pos] = i;
    }
}

// ---------------- GEMM tile body: 16 samples x NCOL cols x 1024 k ----------------
template <int NCOL>
__device__ __forceinline__ void gemm_body(const float* __restrict__ W0, float bias,
                                          const float* sx, float* sl, int wg, int col) {
    unsigned long long acc[4];
    unsigned long long bb = pack2(bias);
    #pragma unroll
    for (int j = 0; j < 4; j++) acc[j] = bb;

    const float* wp = W0 + col;
    float wbuf[GK];
    #pragma unroll
    for (int g = 0; g < GK; g++) wbuf[g] = __ldg(wp + g * NCOL);

    for (int k0 = 0; k0 < NHID; k0 += GK) {
        float wnxt[GK];
        bool more = (k0 + GK < NHID);
        #pragma unroll
        for (int g = 0; g < GK; g++)
            wnxt[g] = more ? __ldg(wp + (k0 + GK + g) * NCOL) : 0.f;
        #pragma unroll
        for (int g = 0; g < GK; g++) {
            unsigned long long wv = pack2(wbuf[g]);
            const ulonglong2* xp = (const ulonglong2*)(sx + (k0 + g) * SBT);
            #pragma unroll
            for (int j = 0; j < 2; j++) {
                ulonglong2 p = xp[wg * 2 + j];
                fma2(acc[2 * j + 0], p.x, wv);
                fma2(acc[2 * j + 1], p.y, wv);
            }
        }
        #pragma unroll
        for (int g = 0; g < GK; g++) wbuf[g] = wnxt[g];
    }

    #pragma unroll
    for (int j = 0; j < 2; j++) {
        int s0 = 8 * wg + 4 * j;
        sl[(s0 + 0) * SLSTRIDE + col] = lo2(acc[2 * j + 0]);
        sl[(s0 + 1) * SLSTRIDE + col] = hi2(acc[2 * j + 0]);
        sl[(s0 + 2) * SLSTRIDE + col] = lo2(acc[2 * j + 1]);
        sl[(s0 + 3) * SLSTRIDE + col] = hi2(acc[2 * j + 1]);
    }
}

// ---------------- persistent main kernel: uniform work pool ----------------
__global__ __launch_bounds__(512, 2) void k_main(const float* __restrict__ x,
                                                 const float* __restrict__ topW,
                                                 const float* __restrict__ topB,
                                                 const float* __restrict__ botW,
                                                 const float* __restrict__ botB,
                                                 float* __restrict__ out) {
    extern __shared__ float smem[];
    float* sx = smem;
    float* sl = smem;
    __shared__ int sid[SBT];
    __shared__ int s_it;

    int tid = threadIdx.x;
    int wg  = tid >> 8;
    int col = tid & 255;
    int wid = tid >> 5, lane = tid & 31;
    int total = NTOPITEMS + g_nbot;

    for (;;) {
        if (tid == 0) s_it = atomicAdd(&g_work, 1);
        __syncthreads();
        int it = s_it;
        if (it >= total) break;   // uniform

        if (it < NTOPITEMS) {
            // ---------------- top tile ----------------
            int base = it * SBT;
            for (int idx = tid; idx < (NHID / 4) * SBT; idx += 512) {
                int u  = idx / (NHID / 4);
                int k4 = (idx % (NHID / 4)) * 4;
                float4 v = *(const float4*)&x[(size_t)(base + u) * NHID + k4];
                sx[(k4 + 0) * SBT + u] = v.x;
                sx[(k4 + 1) * SBT + u] = v.y;
                sx[(k4 + 2) * SBT + u] = v.z;
                sx[(k4 + 3) * SBT + u] = v.w;
            }
            __syncthreads();

            if (col < NCLS) {
                float bias = topB[col];
                __syncwarp();
                // compute into registers, then publish after barrier
                gemm_body<NCLS>(topW, bias, sx, sl, wg, col);
            }
            __syncthreads();

            if (wid < SBT) {
                int i = base + wid;
                float v[7];
                #pragma unroll
                for (int j = 0; j < 7; j++) v[j] = sl[wid * SLSTRIDE + lane + j * 32];
                float m = v[0];
                #pragma unroll
                for (int j = 1; j < 7; j++) m = fmaxf(m, v[j]);
                #pragma unroll
                for (int o = 16; o > 0; o >>= 1) m = fmaxf(m, __shfl_xor_sync(0xffffffffu, m, o));
                float sum = 0.f;
                #pragma unroll
                for (int j = 0; j < 7; j++) sum += __expf(v[j] - m);
                #pragma unroll
                for (int o = 16; o > 0; o >>= 1) sum += __shfl_xor_sync(0xffffffffu, sum, o);
                if (lane == 0) {
                    int c = g_class[i];
                    g_topprob[i] = __expf(sl[wid * SLSTRIDE + c] - m) / sum;
                }
            }
        } else {
            // ---------------- bottom tile ----------------
            int e = g_bitem[it - NTOPITEMS];
            int c = e >> 8, chunk = e & 255;
            int n = g_count[c], off = g_offset[c];
            int nv = min(SBT, n - chunk * SBT);
            const float* Wc = botW + (size_t)c * NHID * NTPC;

            if (tid < SBT) sid[tid] = (tid < nv) ? g_order[off + chunk * SBT + tid] : 0;
            __syncthreads();

            for (int idx = tid; idx < (NHID / 4) * SBT; idx += 512) {
                int u  = idx / (NHID / 4);
                int k4 = (idx % (NHID / 4)) * 4;
                float4 v = (u < nv) ? *(const float4*)&x[(size_t)sid[u] * NHID + k4]
                                    : make_float4(0.f, 0.f, 0.f, 0.f);
                sx[(k4 + 0) * SBT + u] = v.x;
                sx[(k4 + 1) * SBT + u] = v.y;
                sx[(k4 + 2) * SBT + u] = v.z;
                sx[(k4 + 3) * SBT + u] = v.w;
            }
            __syncthreads();

            if (col < NTPC) {
                float bias = botB[c * NTPC + col];
                gemm_body<NTPC>(Wc, bias, sx, sl, wg, col);
            }
            __syncthreads();

            if (wid < nv) {
                int i = sid[wid];
                float v[8];
                #pragma unroll
                for (int j = 0; j < 8; j++) {
                    int idx = lane + j * 32;
                    v[j] = (idx < NTPC) ? sl[wid * SLSTRIDE + idx] : -1e30f;
                }
                float m = v[0];
                #pragma unroll
                for (int j = 1; j < 8; j++) m = fmaxf(m, v[j]);
                #pragma unroll
                for (int o = 16; o > 0; o >>= 1) m = fmaxf(m, __shfl_xor_sync(0xffffffffu, m, o));
                float sum = 0.f;
                #pragma unroll
                for (int j = 0; j < 8; j++) {
                    int idx = lane + j * 32;
                    sum += (idx < NTPC) ? __expf(v[j] - m) : 0.f;
                }
                #pragma unroll
                for (int o = 16; o > 0; o >>= 1) sum += __shfl_xor_sync(0xffffffffu, sum, o);
                if (lane == 0) {
                    int tp = g_tok[i];
                    out[i] = __expf(sl[wid * SLSTRIDE + tp] - m) / sum;   // bottom prob only
                }
            }
        }
        __syncthreads();   // protect smem + s_it before next round
    }
}

// ---------------- finalize: out *= topprob ----------------
__global__ __launch_bounds__(256) void k_final(float* __restrict__ out) {
    int i = blockIdx.x * 256 + threadIdx.x;
    if (i < BATCH) out[i] *= g_topprob[i];
}

// ---------------- launch ----------------
extern "C" void kernel_launch(void* const* d_in, const int* in_sizes, int n_in,
                              void* d_out, int out_size) {
    const float* inputs = (const float*)d_in[0];
    const int*   labels = (const int*)d_in[1];
    const float* topW   = (const float*)d_in[2];
    const float* topB   = (const float*)d_in[3];
    const float* botW   = (const float*)d_in[4];
    const float* botB   = (const float*)d_in[5];
    float*       out    = (float*)d_out;

    cudaFuncSetAttribute(k_main, cudaFuncAttributeMaxDynamicSharedMemorySize, SMEM_BYTES);

    k_prep<<<1, 256>>>(labels);
    k_main<<<MAINBLOCKS, 512, SMEM_BYTES>>>(inputs, topW, topB, botW, botB, out);
    k_final<<<(BATCH + 255) / 256, 256>>>(out);
}